// round 16
// baseline (speedup 1.0000x reference)
#include <cuda_runtime.h>
#include <cuda_bf16.h>
#include <cuda_fp16.h>
#include <cstdint>
#include <cstddef>

// Problem constants
#define RB 64      // batch
#define RT 512     // time steps
#define RI 512     // input dim
#define RH 1024    // hidden dim
#define RO 512     // output dim
#define NBUF 4     // h ring-buffer depth

#define NT1 2048   // GEMM1 tiles: 256 t-pairs x 8 N-tiles
#define NT3 1024   // GEMM3 tiles: 256 t-pairs x 4 N-tiles

// ---------------------------------------------------------------------------
// Scratch (device globals; no allocation allowed)
// ---------------------------------------------------------------------------
__device__ __half g_xp[(size_t)RB * RT * RH];  // x_proj T-MAJOR [t][b][j] (fp16), then hidden
__device__ unsigned g_h2[NBUF * 512 * 64];     // h fp16 k-pairs: [buf][k2][b]
__device__ unsigned g_wflag[128 * 32];         // per-scan-CTA counting write flags (4 quadrants)
__device__ unsigned g_rflag[128 * 32];         // per-scan-CTA read flags
__device__ unsigned g_xpflag[256 * 32];        // per-t-pair x_proj tile counters (target 8)
__device__ unsigned g_ctr1;                    // GEMM1 tile counter
__device__ unsigned g_ctr3;                    // GEMM3 tile counter

// ---------------------------------------------------------------------------
// Helpers
// ---------------------------------------------------------------------------
__device__ __forceinline__ void mma_f16(float* d,
                                        const unsigned* a, unsigned b0, unsigned b1) {
    asm("mma.sync.aligned.m16n8k16.row.col.f32.f16.f16.f32 "
        "{%0,%1,%2,%3},{%4,%5,%6,%7},{%8,%9},{%0,%1,%2,%3};"
        : "+f"(d[0]), "+f"(d[1]), "+f"(d[2]), "+f"(d[3])
        : "r"(a[0]), "r"(a[1]), "r"(a[2]), "r"(a[3]),
          "r"(b0), "r"(b1));
}
__device__ __forceinline__ void mma_f16acc(unsigned* d,
                                           const unsigned* a, unsigned b0, unsigned b1) {
    asm("mma.sync.aligned.m16n8k16.row.col.f16.f16.f16.f16 "
        "{%0,%1},{%2,%3,%4,%5},{%6,%7},{%0,%1};"
        : "+r"(d[0]), "+r"(d[1])
        : "r"(a[0]), "r"(a[1]), "r"(a[2]), "r"(a[3]),
          "r"(b0), "r"(b1));
}
__device__ __forceinline__ void flag_release(unsigned* p, unsigned v) {
    asm volatile("st.release.gpu.global.u32 [%0],%1;" :: "l"(p), "r"(v) : "memory");
}
__device__ __forceinline__ unsigned flag_acquire(const unsigned* p) {
    unsigned v;
    asm volatile("ld.acquire.gpu.global.u32 %0,[%1];" : "=r"(v) : "l"(p) : "memory");
    return v;
}
__device__ __forceinline__ void flag_red_add(unsigned* p) {
    asm volatile("red.release.gpu.global.add.u32 [%0],1;" :: "l"(p) : "memory");
}
__device__ __forceinline__ unsigned ldcg_u32(const unsigned* p) {
    unsigned v;
    asm volatile("ld.global.cg.u32 %0,[%1];" : "=r"(v) : "l"(p));
    return v;
}
__device__ __forceinline__ unsigned h2pack(float a, float b) {
    __half2 h = __floats2half2_rn(a, b);
    return *reinterpret_cast<unsigned*>(&h);
}
__device__ __forceinline__ void st_u16_cs(__half* p, unsigned short v) {
    asm volatile("st.global.cs.u16 [%0],%1;" :: "l"(p), "h"(v) : "memory");
}
__device__ __forceinline__ unsigned short ld_u16_cs(const __half* p) {
    unsigned short v;
    asm volatile("ld.global.cs.u16 %0,[%1];" : "=h"(v) : "l"(p));
    return v;
}

// ---------------------------------------------------------------------------
// Init: zero flags/counters, seed g_h2 buf0 from initial_hidden [b][j]
// ---------------------------------------------------------------------------
__global__ void rnn_init(const float* __restrict__ h0) {
    int bid = blockIdx.x;
    if (bid < 128) {
        int idx = bid * 256 + threadIdx.x;
        int k2 = idx >> 6;
        int b  = idx & 63;
        float v0 = h0[b * RH + 2 * k2];
        float v1 = h0[b * RH + 2 * k2 + 1];
        __half h0a = __float2half_rn(v0), h1a = __float2half_rn(v1);
        g_h2[k2 * 64 + b] = (unsigned)__half_as_ushort(h0a)
                          | ((unsigned)__half_as_ushort(h1a) << 16);
    } else {
        for (int i = threadIdx.x; i < 128 * 32; i += 256) {
            g_wflag[i] = 0;
            g_rflag[i] = 0;
        }
        for (int i = threadIdx.x; i < 256 * 32; i += 256) g_xpflag[i] = 0;
        if (threadIdx.x == 0) { g_ctr1 = 0; g_ctr3 = 0; }
    }
}

// ---------------------------------------------------------------------------
// Fused persistent kernel. SMEM (u32):
//  [0,16384)        W2 (scan weights)
//  [16384,33792)    RedH double buffer
//  [33792,36864)    GEMM As (2 x 1536)
//  [36864,39040)    GEMM Bs (2 x 1088)
// ---------------------------------------------------------------------------
#define SMEM_U32 39040
#define ASTR2 12
#define BSTR2 136

// GEMM1 tile: x_proj(t-major) = inputs @ W_xh + b_h, fp16 out. 256 of 512 thr.
__device__ void gemm1_tile(int tau,
                           const float* __restrict__ A, const float* __restrict__ B,
                           const float* __restrict__ bias, __half* __restrict__ C,
                           unsigned* GAs, unsigned* GBs)
{
    const int tp = tau >> 3, ntile = tau & 7;
    const int tid = threadIdx.x;
    const bool L = tid < 256;
    const int lane = tid & 31, wid = tid >> 5;
    const int g = lane >> 2, tg = lane & 3;
    const int wm = (wid & 3) << 5, wn = ((wid >> 2) & 1) << 6;
    const int bx = ntile << 7;
    const int m0 = tp << 7;

    const int ar = (tid >> 1) & 127, ah = (tid & 1) << 3;
    const int lb = ar & 63, lt = (tp << 1) + (ar >> 6);
    const float* Ag = A + ((size_t)lb * RT + lt) * RI + ah;
    const int bk2 = (tid >> 5) & 7, bn = (tid & 31) << 2;
    const float* Bg = B + (size_t)(2 * bk2) * RH + bx + bn;

    const int nIters = RI >> 4;   // 32
    float4 pa0, pa1, pb0, pb1;
    if (L) {
        pa0 = *(const float4*)(Ag);
        pa1 = *(const float4*)(Ag + 4);
        pb0 = *(const float4*)(Bg);
        pb1 = *(const float4*)(Bg + RH);
        uint4 va = make_uint4(h2pack(pa0.x, pa0.y), h2pack(pa0.z, pa0.w),
                              h2pack(pa1.x, pa1.y), h2pack(pa1.z, pa1.w));
        *(uint4*)&GAs[ar * ASTR2 + (ah >> 1)] = va;
        uint4 vb = make_uint4(h2pack(pb0.x, pb1.x), h2pack(pb0.y, pb1.y),
                              h2pack(pb0.z, pb1.z), h2pack(pb0.w, pb1.w));
        *(uint4*)&GBs[bk2 * BSTR2 + bn] = vb;
    }
    __syncthreads();
    if (L) {
        pa0 = *(const float4*)(Ag + 16);
        pa1 = *(const float4*)(Ag + 20);
        pb0 = *(const float4*)(Bg + (size_t)16 * RH);
        pb1 = *(const float4*)(Bg + (size_t)17 * RH);
    }

    float acc[2][8][4];
#pragma unroll
    for (int i = 0; i < 2; i++)
#pragma unroll
        for (int j = 0; j < 8; j++)
#pragma unroll
            for (int l = 0; l < 4; l++) acc[i][j][l] = 0.f;

    for (int it = 0; it < nIters; ++it) {
        const int cur = it & 1;
        unsigned* Asb = GAs + cur * 1536;
        if (L && it + 1 < nIters) {
            unsigned* Asn = GAs + (cur ^ 1) * 1536;
            unsigned* Bsn = GBs + (cur ^ 1) * 1088;
            uint4 va = make_uint4(h2pack(pa0.x, pa0.y), h2pack(pa0.z, pa0.w),
                                  h2pack(pa1.x, pa1.y), h2pack(pa1.z, pa1.w));
            *(uint4*)&Asn[ar * ASTR2 + (ah >> 1)] = va;
            uint4 vb = make_uint4(h2pack(pb0.x, pb1.x), h2pack(pb0.y, pb1.y),
                                  h2pack(pb0.z, pb1.z), h2pack(pb0.w, pb1.w));
            *(uint4*)&Bsn[bk2 * BSTR2 + bn] = vb;
        }
        if (L) {
            unsigned* Bsb = GBs + cur * 1088;
            unsigned af[2][4], bf[8][2];
#pragma unroll
            for (int mt = 0; mt < 2; mt++) {
                int row = wm + (mt << 4) + g;
                af[mt][0] = Asb[row * ASTR2 + tg];
                af[mt][1] = Asb[(row + 8) * ASTR2 + tg];
                af[mt][2] = Asb[row * ASTR2 + tg + 4];
                af[mt][3] = Asb[(row + 8) * ASTR2 + tg + 4];
            }
#pragma unroll
            for (int nt = 0; nt < 8; nt++) {
                int c = wn + (nt << 3) + g;
                bf[nt][0] = Bsb[tg * BSTR2 + c];
                bf[nt][1] = Bsb[(tg + 4) * BSTR2 + c];
            }
#pragma unroll
            for (int mt = 0; mt < 2; mt++)
#pragma unroll
                for (int nt = 0; nt < 8; nt++)
                    mma_f16(acc[mt][nt], af[mt], bf[nt][0], bf[nt][1]);
        }
        __syncthreads();
        if (L && it + 2 < nIters) {
            int k0 = (it + 2) << 4;
            pa0 = *(const float4*)(Ag + k0);
            pa1 = *(const float4*)(Ag + k0 + 4);
            pb0 = *(const float4*)(Bg + (size_t)k0 * RH);
            pb1 = *(const float4*)(Bg + (size_t)(k0 + 1) * RH);
        }
    }

    if (L) {
#pragma unroll
        for (int mt = 0; mt < 2; mt++) {
            int rr = m0 + wm + (mt << 4) + g;
#pragma unroll
            for (int nt = 0; nt < 8; nt++) {
                int col = bx + wn + (nt << 3) + (tg << 1);
                float b0v = bias[col], b1v = bias[col + 1];
                *(unsigned*)&C[(size_t)rr * RH + col] =
                    h2pack(acc[mt][nt][0] + b0v, acc[mt][nt][1] + b1v);
                *(unsigned*)&C[(size_t)(rr + 8) * RH + col] =
                    h2pack(acc[mt][nt][2] + b0v, acc[mt][nt][3] + b1v);
            }
        }
    }
    __syncthreads();
    if (tid == 0) flag_red_add(&g_xpflag[tp * 32]);
}

// GEMM3 tile: out = hidden(t-major fp16) @ W_hy + b_y. Gated on scan progress.
__device__ void gemm3_tile(int tau,
                           const __half* __restrict__ A, const float* __restrict__ B,
                           const float* __restrict__ bias, float* __restrict__ Cout,
                           unsigned* GAs, unsigned* GBs)
{
    const int tp = tau >> 2, ntile = tau & 3;
    const int tid = threadIdx.x;

    // wait for all 128 scan CTAs to finish steps 2tp, 2tp+1
    {
        const unsigned target = 4u * (unsigned)(2 * tp + 2);
        const unsigned* f = &g_wflag[(tid >> 2) * 32 + ((tid & 3) << 3)];
        while (flag_acquire(f) < target) { }
    }
    __syncthreads();

    const bool L = tid < 256;
    const int lane = tid & 31, wid = tid >> 5;
    const int g = lane >> 2, tg = lane & 3;
    const int wm = (wid & 3) << 5, wn = ((wid >> 2) & 1) << 6;
    const int bx = ntile << 7;
    const int m0 = tp << 7;

    const int ar = (tid >> 1) & 127, ah = (tid & 1) << 3;
    const __half* Ag = A + (size_t)(m0 + ar) * RH + ah;
    const int bk2 = (tid >> 5) & 7, bn = (tid & 31) << 2;
    const float* Bg = B + (size_t)(2 * bk2) * RO + bx + bn;

    const int nIters = RH >> 4;   // 64
    uint4 pa;
    float4 pb0, pb1;
    if (L) {
        pa  = *(const uint4*)(Ag);
        pb0 = *(const float4*)(Bg);
        pb1 = *(const float4*)(Bg + RO);
        *(uint4*)&GAs[ar * ASTR2 + (ah >> 1)] = pa;
        uint4 vb = make_uint4(h2pack(pb0.x, pb1.x), h2pack(pb0.y, pb1.y),
                              h2pack(pb0.z, pb1.z), h2pack(pb0.w, pb1.w));
        *(uint4*)&GBs[bk2 * BSTR2 + bn] = vb;
    }
    __syncthreads();
    if (L) {
        pa  = *(const uint4*)(Ag + 16);
        pb0 = *(const float4*)(Bg + (size_t)16 * RO);
        pb1 = *(const float4*)(Bg + (size_t)17 * RO);
    }

    float acc[2][8][4];
#pragma unroll
    for (int i = 0; i < 2; i++)
#pragma unroll
        for (int j = 0; j < 8; j++)
#pragma unroll
            for (int l = 0; l < 4; l++) acc[i][j][l] = 0.f;

    for (int it = 0; it < nIters; ++it) {
        const int cur = it & 1;
        unsigned* Asb = GAs + cur * 1536;
        if (L && it + 1 < nIters) {
            unsigned* Asn = GAs + (cur ^ 1) * 1536;
            unsigned* Bsn = GBs + (cur ^ 1) * 1088;
            *(uint4*)&Asn[ar * ASTR2 + (ah >> 1)] = pa;
            uint4 vb = make_uint4(h2pack(pb0.x, pb1.x), h2pack(pb0.y, pb1.y),
                                  h2pack(pb0.z, pb1.z), h2pack(pb0.w, pb1.w));
            *(uint4*)&Bsn[bk2 * BSTR2 + bn] = vb;
        }
        if (L) {
            unsigned* Bsb = GBs + cur * 1088;
            unsigned af[2][4], bf[8][2];
#pragma unroll
            for (int mt = 0; mt < 2; mt++) {
                int row = wm + (mt << 4) + g;
                af[mt][0] = Asb[row * ASTR2 + tg];
                af[mt][1] = Asb[(row + 8) * ASTR2 + tg];
                af[mt][2] = Asb[row * ASTR2 + tg + 4];
                af[mt][3] = Asb[(row + 8) * ASTR2 + tg + 4];
            }
#pragma unroll
            for (int nt = 0; nt < 8; nt++) {
                int c = wn + (nt << 3) + g;
                bf[nt][0] = Bsb[tg * BSTR2 + c];
                bf[nt][1] = Bsb[(tg + 4) * BSTR2 + c];
            }
#pragma unroll
            for (int mt = 0; mt < 2; mt++)
#pragma unroll
                for (int nt = 0; nt < 8; nt++)
                    mma_f16(acc[mt][nt], af[mt], bf[nt][0], bf[nt][1]);
        }
        __syncthreads();
        if (L && it + 2 < nIters) {
            int k0 = (it + 2) << 4;
            pa  = *(const uint4*)(Ag + k0);
            pb0 = *(const float4*)(Bg + (size_t)k0 * RO);
            pb1 = *(const float4*)(Bg + (size_t)(k0 + 1) * RO);
        }
    }

    if (L) {
#pragma unroll
        for (int mt = 0; mt < 2; mt++) {
            int rloc = wm + (mt << 4) + g;
#pragma unroll
            for (int rp = 0; rp < 2; rp++) {
                int rl = rloc + rp * 8;
                int tt = (tp << 1) + (rl >> 6), bb = rl & 63;
                float* crow = Cout + ((size_t)bb * RT + tt) * RO;
#pragma unroll
                for (int nt = 0; nt < 8; nt++) {
                    int col = bx + wn + (nt << 3) + (tg << 1);
                    float b0v = bias[col], b1v = bias[col + 1];
                    float2 v = make_float2(acc[mt][nt][rp * 2 + 0] + b0v,
                                           acc[mt][nt][rp * 2 + 1] + b1v);
                    *(float2*)&crow[col] = v;
                }
            }
        }
    }
    __syncthreads();
}

#define SCAN_THREADS 512

__global__ void __launch_bounds__(SCAN_THREADS) rnn_fused(
    const float* __restrict__ inputs, const float* __restrict__ W_xh,
    const float* __restrict__ b_h,   const float* __restrict__ W_hh,
    const float* __restrict__ W_hy,  const float* __restrict__ b_y,
    float* __restrict__ out)
{
    extern __shared__ unsigned smu[];
    unsigned* W2   = smu;
    float*    Red0 = (float*)(smu + 16384);
    float*    Red1 = Red0 + 16 * 544;
    unsigned* GAs  = smu + 33792;
    unsigned* GBs  = smu + 36864;

    const int cta = blockIdx.x;
    const int tid = threadIdx.x;

    if (cta >= 128) {
        // ---------------- WORKER ROLE ----------------
        for (;;) {
            unsigned tau;
            if (tid == 0) tau = atomicAdd(&g_ctr1, 1u);
            tau = __shfl_sync(0xffffffffu, tau, 0);
            __shared__ unsigned s_tau;
            if (tid == 0) s_tau = tau;
            __syncthreads();
            tau = s_tau;
            if (tau >= NT1) break;
            gemm1_tile((int)tau, inputs, W_xh, b_h, g_xp, GAs, GBs);
            __syncthreads();
        }
        for (;;) {
            __shared__ unsigned s_tau3;
            if (tid == 0) s_tau3 = atomicAdd(&g_ctr3, 1u);
            __syncthreads();
            unsigned tau = s_tau3;
            if (tau >= NT3) break;
            gemm3_tile((int)tau, g_xp, W_hy, b_y, out, GAs, GBs);
            __syncthreads();
        }
        return;
    }

    // ---------------- SCAN ROLE (R15 proven core; t-major xp; xpflag gate) ----
    const int g    = cta >> 5;
    const int cg   = cta & 31;
    const int gb0  = g << 4;
    const int gj0  = cg << 5;
    const int lane = tid & 31;
    const int s    = tid >> 5;
    const int tg   = lane & 3;
    const int r    = lane >> 2;
    const int k2base = s << 5;

    for (int i = 0; i < 32; ++i) {
        int idx = i * SCAN_THREADS + tid;
        int k2 = idx >> 5, j = idx & 31;
        float w0 = W_hh[(size_t)(2 * k2) * RH + gj0 + j];
        float w1 = W_hh[(size_t)(2 * k2 + 1) * RH + gj0 + j];
        int dst = k2 * 32 + (j ^ ((k2 & 3) << 3));
        W2[dst] = h2pack(w0, w1);
    }

    const int fb = tid >> 5;
    const int fj = tid & 31;

    const unsigned* prodflag =
        &g_wflag[((g << 5) + (s << 1) + (lane & 1)) * 32 + (((lane >> 1) & 3) << 3)];
    const unsigned* grflag = &g_rflag[((g << 5) + lane) * 32];
    unsigned* my_wflag_q = &g_wflag[cta * 32 + ((s & 3) << 3)];
    unsigned* my_rflag   = &g_rflag[cta * 32];

    __syncthreads();

    for (int t = 0; t < RT; ++t) {
        const unsigned bsrc = (unsigned)(t & 3) * (512 * 64);
        const unsigned bdst = (unsigned)((t + 1) & 3) * (512 * 64);
        float* RedT = (t & 1) ? Red1 : Red0;

        // 1) polls: lanes 0-7 producers (t>0); lane 8 x_proj tile counter
        if (t > 0 && lane < 8) {
            const unsigned tgt = 4u * (unsigned)t;
            while (flag_acquire(prodflag) < tgt) { }
        }
        if (lane == 8) {
            const unsigned* xf = &g_xpflag[(t >> 1) * 32];
            while (flag_acquire(xf) < 8u) { }
        }
        __syncwarp();

        // x_proj (t-major) load — needed only at finalize
        const size_t xpi = ((size_t)t * 64 + gb0 + fb) * RH + gj0 + fj;
        const float xpv = __half2float(__ushort_as_half(ld_u16_cs(&g_xp[xpi])));

        unsigned rv = 0;
        if (s == 15) rv = flag_acquire(grflag);

        // 2) LDG A-fragments
        unsigned ah[4][4];
#pragma unroll
        for (int cc = 0; cc < 4; ++cc) {
            const int k2a = k2base + (cc << 3) + tg;
            ah[cc][0] = ldcg_u32(&g_h2[bsrc + k2a * 64 + gb0 + r]);
            ah[cc][1] = ldcg_u32(&g_h2[bsrc + k2a * 64 + gb0 + r + 8]);
            ah[cc][2] = ldcg_u32(&g_h2[bsrc + (k2a + 4) * 64 + gb0 + r]);
            ah[cc][3] = ldcg_u32(&g_h2[bsrc + (k2a + 4) * 64 + gb0 + r + 8]);
        }

        // 3) 16 MMAs, fp16-acc k=32 windows promoted to fp32
        float acc[4][4];
#pragma unroll
        for (int nt = 0; nt < 4; nt++)
#pragma unroll
            for (int l = 0; l < 4; l++) acc[nt][l] = 0.f;

#pragma unroll
        for (int pr = 0; pr < 2; ++pr) {
            unsigned hacc[4][2];
#pragma unroll
            for (int nt = 0; nt < 4; nt++) { hacc[nt][0] = 0u; hacc[nt][1] = 0u; }
#pragma unroll
            for (int ci = 0; ci < 2; ++ci) {
                const int cc = (pr << 1) + ci;
                const int k2a = k2base + (cc << 3) + tg;
#pragma unroll
                for (int nt = 0; nt < 4; ++nt) {
                    const int c0 = ((nt << 3) + r) ^ (tg << 3);
                    mma_f16acc(hacc[nt], ah[cc],
                               W2[k2a * 32 + c0], W2[(k2a + 4) * 32 + c0]);
                }
            }
#pragma unroll
            for (int nt = 0; nt < 4; ++nt) {
                float2 a01 = __half22float2(*reinterpret_cast<__half2*>(&hacc[nt][0]));
                float2 a23 = __half22float2(*reinterpret_cast<__half2*>(&hacc[nt][1]));
                acc[nt][0] += a01.x; acc[nt][1] += a01.y;
                acc[nt][2] += a23.x; acc[nt][3] += a23.y;
            }
        }

        // 4) partials
        {
            float* rp = RedT + s * 544;
#pragma unroll
            for (int nt = 0; nt < 4; ++nt) {
                int j0 = (nt << 3) + (tg << 1);
                rp[j0 * 17 + r]            = acc[nt][0];
                rp[(j0 + 1) * 17 + r]      = acc[nt][1];
                rp[j0 * 17 + r + 8]        = acc[nt][2];
                rp[(j0 + 1) * 17 + r + 8]  = acc[nt][3];
            }
        }
        // 5) back-pressure
        if (s == 15) {
            int tgt = t - 2;
            if (tgt > 0) {
                while (!__all_sync(0xffffffffu, (int)rv >= tgt)) {
                    rv = flag_acquire(grflag);
                }
            }
        }
        __syncthreads();

        if (tid == 0) flag_release(my_rflag, (unsigned)(t + 1));

        // 7) finalize
        {
            float v = 0.f;
            const float* rp = RedT + fj * 17 + fb;
#pragma unroll
            for (int ss = 0; ss < 16; ++ss) v += rp[ss * 544];
            float hv = tanhf(v + xpv);

            unsigned short hb = __half_as_ushort(__float2half_rn(hv));
            unsigned nb = __shfl_down_sync(0xffffffffu, (unsigned)hb, 1);
            if ((fj & 1) == 0) {
                int k2g = (cg << 4) + (fj >> 1);
                g_h2[bdst + k2g * 64 + gb0 + fb] =
                    (unsigned)hb | ((nb & 0xffffu) << 16);
            }
            st_u16_cs(&g_xp[xpi], hb);   // hidden history BEFORE wflag release
            __syncwarp();
            if (lane == 0) flag_red_add(my_wflag_q);

            if (t == RT - 1)
                out[(size_t)RB * RT * RO + (size_t)(gb0 + fb) * RH + gj0 + fj] = hv;
        }
    }

    // scan CTAs join GEMM3 tile stealing
    for (;;) {
        __shared__ unsigned s_tau3b;
        if (tid == 0) s_tau3b = atomicAdd(&g_ctr3, 1u);
        __syncthreads();
        unsigned tau = s_tau3b;
        if (tau >= NT3) break;
        gemm3_tile((int)tau, g_xp, W_hy, b_y, out, GAs, GBs);
        __syncthreads();
    }
}

// ---------------------------------------------------------------------------
// Launch
// ---------------------------------------------------------------------------
extern "C" void kernel_launch(void* const* d_in, const int* in_sizes, int n_in,
                              void* d_out, int out_size)
{
    const float* inputs = (const float*)d_in[0];
    const float* h0     = (const float*)d_in[1];
    const float* W_xh   = (const float*)d_in[2];
    const float* W_hh   = (const float*)d_in[3];
    const float* W_hy   = (const float*)d_in[4];
    const float* b_h    = (const float*)d_in[5];
    const float* b_y    = (const float*)d_in[6];
    float* out = (float*)d_out;

    cudaFuncSetAttribute(rnn_fused,
                         cudaFuncAttributeMaxDynamicSharedMemorySize,
                         SMEM_U32 * (int)sizeof(unsigned));

    // 0) reset flags/counters, seed h0
    rnn_init<<<129, 256>>>(h0);

    // 1) fused: GEMM1 workers + persistent scan + GEMM3 stealing
    rnn_fused<<<152, SCAN_THREADS, SMEM_U32 * sizeof(unsigned)>>>(
        inputs, W_xh, b_h, W_hh, W_hy, b_y, out);
}

// round 17
// speedup vs baseline: 1.3591x; 1.3591x over previous
#include <cuda_runtime.h>
#include <cuda_bf16.h>
#include <cuda_fp16.h>
#include <cstdint>
#include <cstddef>

// Problem constants
#define RB 64      // batch
#define RT 512     // time steps
#define RI 512     // input dim
#define RH 1024    // hidden dim
#define RO 512     // output dim
#define NBUF 4     // h ring-buffer depth

// ---------------------------------------------------------------------------
// Scratch (device globals; no allocation allowed)
// ---------------------------------------------------------------------------
__device__ __half g_xp[(size_t)RB * RT * RH];  // x_proj (fp16), then hidden states (in place)
__device__ unsigned g_h2[NBUF * 512 * 64];     // h fp16 k-pairs: [buf][k2][b]
__device__ unsigned g_wflag[128 * 32];         // per-CTA counting write flags (4 quadrants)
__device__ unsigned g_rflag[128 * 32];         // per-CTA read flags, 128B apart

// ---------------------------------------------------------------------------
// Helpers
// ---------------------------------------------------------------------------
__device__ __forceinline__ void mma_f16(float* d,
                                        const unsigned* a, unsigned b0, unsigned b1) {
    asm("mma.sync.aligned.m16n8k16.row.col.f32.f16.f16.f32 "
        "{%0,%1,%2,%3},{%4,%5,%6,%7},{%8,%9},{%0,%1,%2,%3};"
        : "+f"(d[0]), "+f"(d[1]), "+f"(d[2]), "+f"(d[3])
        : "r"(a[0]), "r"(a[1]), "r"(a[2]), "r"(a[3]),
          "r"(b0), "r"(b1));
}
__device__ __forceinline__ void mma_f16acc(unsigned* d,
                                           const unsigned* a, unsigned b0, unsigned b1) {
    asm("mma.sync.aligned.m16n8k16.row.col.f16.f16.f16.f16 "
        "{%0,%1},{%2,%3,%4,%5},{%6,%7},{%0,%1};"
        : "+r"(d[0]), "+r"(d[1])
        : "r"(a[0]), "r"(a[1]), "r"(a[2]), "r"(a[3]),
          "r"(b0), "r"(b1));
}
__device__ __forceinline__ void flag_release(unsigned* p, unsigned v) {
    asm volatile("st.release.gpu.global.u32 [%0],%1;" :: "l"(p), "r"(v) : "memory");
}
__device__ __forceinline__ unsigned flag_acquire(const unsigned* p) {
    unsigned v;
    asm volatile("ld.acquire.gpu.global.u32 %0,[%1];" : "=r"(v) : "l"(p) : "memory");
    return v;
}
__device__ __forceinline__ void flag_red_add(unsigned* p) {
    asm volatile("red.release.gpu.global.add.u32 [%0],1;" :: "l"(p) : "memory");
}
__device__ __forceinline__ unsigned ldcg_u32(const unsigned* p) {
    unsigned v;
    asm volatile("ld.global.cg.u32 %0,[%1];" : "=r"(v) : "l"(p));
    return v;
}
__device__ __forceinline__ unsigned h2pack(float a, float b) {
    __half2 h = __floats2half2_rn(a, b);   // low = a, high = b
    return *reinterpret_cast<unsigned*>(&h);
}
__device__ __forceinline__ void st_u16_cs(__half* p, unsigned short v) {
    asm volatile("st.global.cs.u16 [%0],%1;" :: "l"(p), "h"(v) : "memory");
}
__device__ __forceinline__ unsigned short ld_u16_cs(const __half* p) {
    unsigned short v;
    asm volatile("ld.global.cs.u16 %0,[%1];" : "=h"(v) : "l"(p));
    return v;
}

// ---------------------------------------------------------------------------
// Init: zero flags, seed g_h2 buf0 from initial_hidden [b][j]
// ---------------------------------------------------------------------------
__global__ void rnn_init(const float* __restrict__ h0) {
    int bid = blockIdx.x;
    if (bid < 128) {
        int idx = bid * 256 + threadIdx.x;      // 0..32767 pairs
        int k2 = idx >> 6;                       // 0..511
        int b  = idx & 63;
        float v0 = h0[b * RH + 2 * k2];
        float v1 = h0[b * RH + 2 * k2 + 1];
        g_h2[k2 * 64 + b] = h2pack(v0, v1);
    } else {
        for (int i = threadIdx.x; i < 128 * 32; i += 256) {
            g_wflag[i] = 0;
            g_rflag[i] = 0;
        }
    }
}

// ---------------------------------------------------------------------------
// FP16 tensor-core GEMM, DOUBLE-BUFFERED, BK=32 (one sync per 32 MMAs):
//   C[M,N](fp16) = A[M,K](fp32) @ B[K,N](fp32) + bias[N]
// 128x128x32 staged tile, 256 thr = 8 warps (4x2), warp tile 32x64.
// As stride 20 (conflict-free A-frags), Bs stride 136 (conflict-free B-frags).
// ---------------------------------------------------------------------------
#define ASTR3 20
#define BSTR3 136
__global__ void __launch_bounds__(256) gemm_f16_bias_h16out(
    int M, int N, int K,
    const float* __restrict__ A, const float* __restrict__ B,
    const float* __restrict__ bias, __half* __restrict__ C)
{
    __shared__ unsigned As[2][128 * ASTR3];   // 2 x 10 KB
    __shared__ unsigned Bs[2][16 * BSTR3];    // 2 x 8.5 KB

    const int tid  = threadIdx.x;
    const int lane = tid & 31, wid = tid >> 5;
    const int g  = lane >> 2, tg = lane & 3;
    const int wm = (wid & 3) << 5;
    const int wn = (wid >> 2) << 6;
    const int bx = blockIdx.x << 7, by = blockIdx.y << 7;

    // A loader: row ar, k offset ah16 (0 or 16)
    const int ar = tid >> 1, ah16 = (tid & 1) << 4;
    const float* Ag = A + (size_t)(by + ar) * K + ah16;
    // B loader: k2 rows bk2, bk2+8; col quad bn
    const int bk2 = tid >> 5, bn = (tid & 31) << 2;
    const float* Bg = B + (size_t)(2 * bk2) * N + bx + bn;

    const int nIters = K >> 5;   // 32 k per iter

    float4 pa0, pa1, pa2, pa3, pb0, pb1, pb2, pb3;

#define G1_LOAD(k0)  do { \
        pa0 = *(const float4*)(Ag + (k0));        \
        pa1 = *(const float4*)(Ag + (k0) + 4);    \
        pa2 = *(const float4*)(Ag + (k0) + 8);    \
        pa3 = *(const float4*)(Ag + (k0) + 12);   \
        pb0 = *(const float4*)(Bg + (size_t)(k0) * N);        \
        pb1 = *(const float4*)(Bg + (size_t)((k0) + 1) * N);  \
        pb2 = *(const float4*)(Bg + (size_t)((k0) + 16) * N); \
        pb3 = *(const float4*)(Bg + (size_t)((k0) + 17) * N); \
    } while (0)

#define G1_STORE(buf) do { \
        uint4 va0 = make_uint4(h2pack(pa0.x, pa0.y), h2pack(pa0.z, pa0.w), \
                               h2pack(pa1.x, pa1.y), h2pack(pa1.z, pa1.w)); \
        uint4 va1 = make_uint4(h2pack(pa2.x, pa2.y), h2pack(pa2.z, pa2.w), \
                               h2pack(pa3.x, pa3.y), h2pack(pa3.z, pa3.w)); \
        *(uint4*)&As[buf][ar * ASTR3 + (ah16 >> 1)]     = va0; \
        *(uint4*)&As[buf][ar * ASTR3 + (ah16 >> 1) + 4] = va1; \
        uint4 vb0 = make_uint4(h2pack(pb0.x, pb1.x), h2pack(pb0.y, pb1.y), \
                               h2pack(pb0.z, pb1.z), h2pack(pb0.w, pb1.w)); \
        uint4 vb1 = make_uint4(h2pack(pb2.x, pb3.x), h2pack(pb2.y, pb3.y), \
                               h2pack(pb2.z, pb3.z), h2pack(pb2.w, pb3.w)); \
        *(uint4*)&Bs[buf][bk2 * BSTR3 + bn]       = vb0; \
        *(uint4*)&Bs[buf][(bk2 + 8) * BSTR3 + bn] = vb1; \
    } while (0)

    G1_LOAD(0);
    G1_STORE(0);
    __syncthreads();
    if (nIters > 1) G1_LOAD(32);

    float acc[2][8][4];
#pragma unroll
    for (int i = 0; i < 2; i++)
#pragma unroll
        for (int j = 0; j < 8; j++)
#pragma unroll
            for (int l = 0; l < 4; l++) acc[i][j][l] = 0.f;

    for (int it = 0; it < nIters; ++it) {
        const int cur = it & 1;
        if (it + 1 < nIters) G1_STORE(cur ^ 1);

#pragma unroll
        for (int ks2 = 0; ks2 < 16; ks2 += 8) {
            unsigned af[2][4], bf[8][2];
#pragma unroll
            for (int mt = 0; mt < 2; mt++) {
                int row = wm + (mt << 4) + g;
                af[mt][0] = As[cur][row * ASTR3 + ks2 + tg];
                af[mt][1] = As[cur][(row + 8) * ASTR3 + ks2 + tg];
                af[mt][2] = As[cur][row * ASTR3 + ks2 + tg + 4];
                af[mt][3] = As[cur][(row + 8) * ASTR3 + ks2 + tg + 4];
            }
#pragma unroll
            for (int nt = 0; nt < 8; nt++) {
                int c = wn + (nt << 3) + g;
                bf[nt][0] = Bs[cur][(ks2 + tg) * BSTR3 + c];
                bf[nt][1] = Bs[cur][(ks2 + tg + 4) * BSTR3 + c];
            }
#pragma unroll
            for (int mt = 0; mt < 2; mt++)
#pragma unroll
                for (int nt = 0; nt < 8; nt++)
                    mma_f16(acc[mt][nt], af[mt], bf[nt][0], bf[nt][1]);
        }
        __syncthreads();

        if (it + 2 < nIters) G1_LOAD((it + 2) << 5);
    }
#undef G1_LOAD
#undef G1_STORE

#pragma unroll
    for (int mt = 0; mt < 2; mt++) {
        int r0 = by + wm + (mt << 4) + g;
#pragma unroll
        for (int nt = 0; nt < 8; nt++) {
            int col = bx + wn + (nt << 3) + (tg << 1);
            float b0v = bias[col], b1v = bias[col + 1];
            *(unsigned*)&C[(size_t)r0 * N + col] =
                h2pack(acc[mt][nt][0] + b0v, acc[mt][nt][1] + b1v);
            *(unsigned*)&C[(size_t)(r0 + 8) * N + col] =
                h2pack(acc[mt][nt][2] + b0v, acc[mt][nt][3] + b1v);
        }
    }
}

// ---------------------------------------------------------------------------
// FP16 tensor-core GEMM, fp16 A input, fp32 output, BK=32 double-buffered.
// ---------------------------------------------------------------------------
__global__ void __launch_bounds__(256) gemm_f16A_bias(
    int M, int N, int K,
    const __half* __restrict__ A, const float* __restrict__ B,
    const float* __restrict__ bias, float* __restrict__ C)
{
    __shared__ unsigned As[2][128 * ASTR3];
    __shared__ unsigned Bs[2][16 * BSTR3];

    const int tid  = threadIdx.x;
    const int lane = tid & 31, wid = tid >> 5;
    const int g  = lane >> 2, tg = lane & 3;
    const int wm = (wid & 3) << 5;
    const int wn = (wid >> 2) << 6;
    const int bx = blockIdx.x << 7, by = blockIdx.y << 7;

    const int ar = tid >> 1, ah16 = (tid & 1) << 4;
    const __half* Ag = A + (size_t)(by + ar) * K + ah16;
    const int bk2 = tid >> 5, bn = (tid & 31) << 2;
    const float* Bg = B + (size_t)(2 * bk2) * N + bx + bn;

    const int nIters = K >> 5;

    uint4  pa0, pa1;
    float4 pb0, pb1, pb2, pb3;

#define G3_LOAD(k0)  do { \
        pa0 = *(const uint4*)(Ag + (k0));       \
        pa1 = *(const uint4*)(Ag + (k0) + 8);   \
        pb0 = *(const float4*)(Bg + (size_t)(k0) * N);        \
        pb1 = *(const float4*)(Bg + (size_t)((k0) + 1) * N);  \
        pb2 = *(const float4*)(Bg + (size_t)((k0) + 16) * N); \
        pb3 = *(const float4*)(Bg + (size_t)((k0) + 17) * N); \
    } while (0)

#define G3_STORE(buf) do { \
        *(uint4*)&As[buf][ar * ASTR3 + (ah16 >> 1)]     = pa0; \
        *(uint4*)&As[buf][ar * ASTR3 + (ah16 >> 1) + 4] = pa1; \
        uint4 vb0 = make_uint4(h2pack(pb0.x, pb1.x), h2pack(pb0.y, pb1.y), \
                               h2pack(pb0.z, pb1.z), h2pack(pb0.w, pb1.w)); \
        uint4 vb1 = make_uint4(h2pack(pb2.x, pb3.x), h2pack(pb2.y, pb3.y), \
                               h2pack(pb2.z, pb3.z), h2pack(pb2.w, pb3.w)); \
        *(uint4*)&Bs[buf][bk2 * BSTR3 + bn]       = vb0; \
        *(uint4*)&Bs[buf][(bk2 + 8) * BSTR3 + bn] = vb1; \
    } while (0)

    G3_LOAD(0);
    G3_STORE(0);
    __syncthreads();
    if (nIters > 1) G3_LOAD(32);

    float acc[2][8][4];
#pragma unroll
    for (int i = 0; i < 2; i++)
#pragma unroll
        for (int j = 0; j < 8; j++)
#pragma unroll
            for (int l = 0; l < 4; l++) acc[i][j][l] = 0.f;

    for (int it = 0; it < nIters; ++it) {
        const int cur = it & 1;
        if (it + 1 < nIters) G3_STORE(cur ^ 1);

#pragma unroll
        for (int ks2 = 0; ks2 < 16; ks2 += 8) {
            unsigned af[2][4], bf[8][2];
#pragma unroll
            for (int mt = 0; mt < 2; mt++) {
                int row = wm + (mt << 4) + g;
                af[mt][0] = As[cur][row * ASTR3 + ks2 + tg];
                af[mt][1] = As[cur][(row + 8) * ASTR3 + ks2 + tg];
                af[mt][2] = As[cur][row * ASTR3 + ks2 + tg + 4];
                af[mt][3] = As[cur][(row + 8) * ASTR3 + ks2 + tg + 4];
            }
#pragma unroll
            for (int nt = 0; nt < 8; nt++) {
                int c = wn + (nt << 3) + g;
                bf[nt][0] = Bs[cur][(ks2 + tg) * BSTR3 + c];
                bf[nt][1] = Bs[cur][(ks2 + tg + 4) * BSTR3 + c];
            }
#pragma unroll
            for (int mt = 0; mt < 2; mt++)
#pragma unroll
                for (int nt = 0; nt < 8; nt++)
                    mma_f16(acc[mt][nt], af[mt], bf[nt][0], bf[nt][1]);
        }
        __syncthreads();

        if (it + 2 < nIters) G3_LOAD((it + 2) << 5);
    }
#undef G3_LOAD
#undef G3_STORE

#pragma unroll
    for (int mt = 0; mt < 2; mt++) {
        int r0 = by + wm + (mt << 4) + g;
#pragma unroll
        for (int nt = 0; nt < 8; nt++) {
            int col = bx + wn + (nt << 3) + (tg << 1);
            float b0v = bias[col], b1v = bias[col + 1];
            float2 v0 = make_float2(acc[mt][nt][0] + b0v, acc[mt][nt][1] + b1v);
            float2 v1 = make_float2(acc[mt][nt][2] + b0v, acc[mt][nt][3] + b1v);
            *(float2*)&C[(size_t)r0 * N + col]       = v0;
            *(float2*)&C[(size_t)(r0 + 8) * N + col] = v1;
        }
    }
}

// ---------------------------------------------------------------------------
// Persistent recurrent scan — R15 VERBATIM (proven best).
// ---------------------------------------------------------------------------
#define SCAN_THREADS 512
#define SMEM_U32 (16384 + 2 * 16 * 544)

__global__ void __launch_bounds__(SCAN_THREADS) rnn_scan_kernel(
    const float* __restrict__ W_hh, float* __restrict__ out)
{
    extern __shared__ unsigned smu[];
    unsigned* W2   = smu;
    float*    Red0 = (float*)(smu + 16384);
    float*    Red1 = Red0 + 16 * 544;

    const int cta = blockIdx.x;
    const int g   = cta >> 5;
    const int cg  = cta & 31;
    const int gb0 = g << 4;
    const int gj0 = cg << 5;
    const int tid = threadIdx.x;
    const int lane = tid & 31;
    const int s    = tid >> 5;
    const int tg   = lane & 3;
    const int r    = lane >> 2;
    const int k2base = s << 5;

    for (int i = 0; i < 32; ++i) {
        int idx = i * SCAN_THREADS + tid;
        int k2 = idx >> 5, j = idx & 31;
        float w0 = W_hh[(size_t)(2 * k2) * RH + gj0 + j];
        float w1 = W_hh[(size_t)(2 * k2 + 1) * RH + gj0 + j];
        int dst = k2 * 32 + (j ^ ((k2 & 3) << 3));
        W2[dst] = h2pack(w0, w1);
    }

    const int fb = tid >> 5;
    const int fj = tid & 31;

    const unsigned* prodflag =
        &g_wflag[((g << 5) + (s << 1) + (lane & 1)) * 32 + (((lane >> 1) & 3) << 3)];
    const unsigned* grflag = &g_rflag[((g << 5) + lane) * 32];
    unsigned* my_wflag_q = &g_wflag[cta * 32 + ((s & 3) << 3)];
    unsigned* my_rflag   = &g_rflag[cta * 32];

    __syncthreads();

    for (int t = 0; t < RT; ++t) {
        const unsigned bsrc = (unsigned)(t & 3) * (512 * 64);
        const unsigned bdst = (unsigned)((t + 1) & 3) * (512 * 64);
        float* RedT = (t & 1) ? Red1 : Red0;

        const size_t xpi = ((size_t)(gb0 + fb) * RT + t) * RH + gj0 + fj;
        const float xpv = __half2float(__ushort_as_half(ld_u16_cs(&g_xp[xpi])));

        if (t > 0) {
            const unsigned tgt = 4u * (unsigned)t;
            if (lane < 8) {
                while (flag_acquire(prodflag) < tgt) { }
            }
            __syncwarp();
        }
        unsigned rv = 0;
        if (s == 15) rv = flag_acquire(grflag);

        unsigned ah[4][4];
#pragma unroll
        for (int cc = 0; cc < 4; ++cc) {
            const int k2a = k2base + (cc << 3) + tg;
            ah[cc][0] = ldcg_u32(&g_h2[bsrc + k2a * 64 + gb0 + r]);
            ah[cc][1] = ldcg_u32(&g_h2[bsrc + k2a * 64 + gb0 + r + 8]);
            ah[cc][2] = ldcg_u32(&g_h2[bsrc + (k2a + 4) * 64 + gb0 + r]);
            ah[cc][3] = ldcg_u32(&g_h2[bsrc + (k2a + 4) * 64 + gb0 + r + 8]);
        }

        float acc[4][4];
#pragma unroll
        for (int nt = 0; nt < 4; nt++)
#pragma unroll
            for (int l = 0; l < 4; l++) acc[nt][l] = 0.f;

#pragma unroll
        for (int pr = 0; pr < 2; ++pr) {
            unsigned hacc[4][2];
#pragma unroll
            for (int nt = 0; nt < 4; nt++) { hacc[nt][0] = 0u; hacc[nt][1] = 0u; }
#pragma unroll
            for (int ci = 0; ci < 2; ++ci) {
                const int cc = (pr << 1) + ci;
                const int k2a = k2base + (cc << 3) + tg;
#pragma unroll
                for (int nt = 0; nt < 4; ++nt) {
                    const int c0 = ((nt << 3) + r) ^ (tg << 3);
                    mma_f16acc(hacc[nt], ah[cc],
                               W2[k2a * 32 + c0], W2[(k2a + 4) * 32 + c0]);
                }
            }
#pragma unroll
            for (int nt = 0; nt < 4; ++nt) {
                float2 a01 = __half22float2(*reinterpret_cast<__half2*>(&hacc[nt][0]));
                float2 a23 = __half22float2(*reinterpret_cast<__half2*>(&hacc[nt][1]));
                acc[nt][0] += a01.x; acc[nt][1] += a01.y;
                acc[nt][2] += a23.x; acc[nt][3] += a23.y;
            }
        }

        {
            float* rp = RedT + s * 544;
#pragma unroll
            for (int nt = 0; nt < 4; ++nt) {
                int j0 = (nt << 3) + (tg << 1);
                rp[j0 * 17 + r]            = acc[nt][0];
                rp[(j0 + 1) * 17 + r]      = acc[nt][1];
                rp[j0 * 17 + r + 8]        = acc[nt][2];
                rp[(j0 + 1) * 17 + r + 8]  = acc[nt][3];
            }
        }
        if (s == 15) {
            int tgt = t - 2;
            if (tgt > 0) {
                while (!__all_sync(0xffffffffu, (int)rv >= tgt)) {
                    rv = flag_acquire(grflag);
                }
            }
        }
        __syncthreads();

        if (tid == 0) flag_release(my_rflag, (unsigned)(t + 1));

        {
            float v = 0.f;
            const float* rp = RedT + fj * 17 + fb;
#pragma unroll
            for (int ss = 0; ss < 16; ++ss) v += rp[ss * 544];
            float hv = tanhf(v + xpv);

            unsigned short hb = __half_as_ushort(__float2half_rn(hv));
            unsigned nb = __shfl_down_sync(0xffffffffu, (unsigned)hb, 1);
            if ((fj & 1) == 0) {
                int k2g = (cg << 4) + (fj >> 1);
                g_h2[bdst + k2g * 64 + gb0 + fb] =
                    (unsigned)hb | ((nb & 0xffffu) << 16);
            }
            __syncwarp();
            if (lane == 0) flag_red_add(my_wflag_q);

            st_u16_cs(&g_xp[xpi], hb);
            if (t == RT - 1)
                out[(size_t)RB * RT * RO + (size_t)(gb0 + fb) * RH + gj0 + fj] = hv;
        }
    }
}

// ---------------------------------------------------------------------------
// Launch
// ---------------------------------------------------------------------------
extern "C" void kernel_launch(void* const* d_in, const int* in_sizes, int n_in,
                              void* d_out, int out_size)
{
    const float* inputs = (const float*)d_in[0];
    const float* h0     = (const float*)d_in[1];
    const float* W_xh   = (const float*)d_in[2];
    const float* W_hh   = (const float*)d_in[3];
    const float* W_hy   = (const float*)d_in[4];
    const float* b_h    = (const float*)d_in[5];
    const float* b_y    = (const float*)d_in[6];
    float* out = (float*)d_out;

    void* xp_ptr = nullptr;
    cudaGetSymbolAddress(&xp_ptr, g_xp);
    __half* xp = (__half*)xp_ptr;

    cudaFuncSetAttribute(rnn_scan_kernel,
                         cudaFuncAttributeMaxDynamicSharedMemorySize,
                         SMEM_U32 * (int)sizeof(unsigned));

    // 0) reset flags, seed h0 as fp16 pairs
    rnn_init<<<129, 256>>>(h0);

    // 1) x_proj = inputs @ W_xh + b_h   (fp16 TC, BK=32 double-buffered)
    gemm_f16_bias_h16out<<<dim3(RH / 128, (RB * RT) / 128), 256>>>(
        RB * RT, RH, RI, inputs, W_xh, b_h, xp);

    // 2) persistent recurrent scan (R15 verbatim)
    rnn_scan_kernel<<<128, SCAN_THREADS, SMEM_U32 * sizeof(unsigned)>>>(W_hh, out);

    // 3) outputs = hidden_states(fp16) @ W_hy + b_y   (fp16 TC, BK=32)
    gemm_f16A_bias<<<dim3(RO / 128, (RB * RT) / 128), 256>>>(
        RB * RT, RO, RH, xp, W_hy, b_y, out);
}